// round 8
// baseline (speedup 1.0000x reference)
#include <cuda_runtime.h>

#define HIDDEN 51
#define JP 64
#define KQ 13            // k-rows per quarter; 4*13 = 52 = rows 0..50 U + row 51 bias
#define KROWS 52
#define L_SEQ 1000
#define NBLK 128
#define THREADS 512      // 2 groups x 256; group = 4 batches, k in 4 quarters (in-warp)

typedef unsigned long long ull;

// Gate-interleaved weights: g_U4[row*JP + j] = (i,f,g,o); row 51 = combined bias
__device__ float4 g_U4[KROWS * JP];
__device__ float4 g_W4[JP];   // x weights per j
__device__ float  g_L[JP];    // lin_w per j

// ---------- f32x2 helpers ----------
__device__ __forceinline__ ull pk2(float lo, float hi) {
    ull r; asm("mov.b64 %0, {%1, %2};" : "=l"(r) : "f"(lo), "f"(hi)); return r;
}
__device__ __forceinline__ void up2(float& lo, float& hi, ull v) {
    asm("mov.b64 {%0, %1}, %2;" : "=f"(lo), "=f"(hi) : "l"(v));
}
__device__ __forceinline__ ull f2fma(ull a, ull b, ull c) {
    ull d; asm("fma.rn.f32x2 %0, %1, %2, %3;" : "=l"(d) : "l"(a), "l"(b), "l"(c)); return d;
}
__device__ __forceinline__ ull f2add(ull a, ull b) {
    ull d; asm("add.rn.f32x2 %0, %1, %2;" : "=l"(d) : "l"(a), "l"(b)); return d;
}
__device__ __forceinline__ ull shfl_xor64(ull v, int m) {
    unsigned lo, hi;
    asm("mov.b64 {%0,%1}, %2;" : "=r"(lo), "=r"(hi) : "l"(v));
    lo = __shfl_xor_sync(0xffffffffu, lo, m);
    hi = __shfl_xor_sync(0xffffffffu, hi, m);
    ull r; asm("mov.b64 %0, {%1,%2};" : "=l"(r) : "r"(lo), "r"(hi));
    return r;
}
// accurate fast tanh: 1 - 2/(exp(2x)+1); saturates correctly at +-inf
__device__ __forceinline__ float fast_tanh(float xv) {
    float e;
    asm("ex2.approx.f32 %0, %1;" : "=f"(e) : "f"(xv * 2.8853900817779268f));
    float r;
    asm("rcp.approx.f32 %0, %1;" : "=f"(r) : "f"(e + 1.0f));
    return fmaf(-2.0f, r, 1.0f);
}
__device__ __forceinline__ void group_bar(int barid) {
    asm volatile("bar.sync %0, %1;" :: "r"(barid), "r"(256) : "memory");
}

// ---------- prep ----------
__global__ void prep_kernel(const float* __restrict__ W_w, const float* __restrict__ W_b,
                            const float* __restrict__ U_w, const float* __restrict__ U_b,
                            const float* __restrict__ lin_w) {
    int i = blockIdx.x * 128 + threadIdx.x;   // 0 .. 3327 (52 rows x 64 j)
    if (i >= KROWS * JP) return;
    int k = i >> 6, j = i & 63;
    float4 u = make_float4(0.f, 0.f, 0.f, 0.f);
    if (j < HIDDEN) {
        if (k < HIDDEN) {
            u.x = U_w[(0 * HIDDEN + j) * HIDDEN + k];
            u.y = U_w[(1 * HIDDEN + j) * HIDDEN + k];
            u.z = U_w[(2 * HIDDEN + j) * HIDDEN + k];
            u.w = U_w[(3 * HIDDEN + j) * HIDDEN + k];
        } else {                              // row 51 = combined bias (h == 1)
            u.x = W_b[0 * HIDDEN + j] + U_b[0 * HIDDEN + j];
            u.y = W_b[1 * HIDDEN + j] + U_b[1 * HIDDEN + j];
            u.z = W_b[2 * HIDDEN + j] + U_b[2 * HIDDEN + j];
            u.w = W_b[3 * HIDDEN + j] + U_b[3 * HIDDEN + j];
        }
    }
    g_U4[i] = u;
    if (i < JP) {
        float4 w = make_float4(0.f, 0.f, 0.f, 0.f);
        float lw = 0.f;
        if (i < HIDDEN) {
            w.x = W_w[0 * HIDDEN + i]; w.y = W_w[1 * HIDDEN + i];
            w.z = W_w[2 * HIDDEN + i]; w.w = W_w[3 * HIDDEN + i];
            lw = lin_w[i];
        }
        g_W4[i] = w; g_L[i] = lw;
    }
}

// ---------- main ----------
// 512 threads = 2 groups x 256; group = 4 batches.
// Lane layout: lane = q*8 + j8 (q = k-quarter AND owned batch), j = warp*8 + j8.
// All 4 quarters of a j live in ONE warp -> combine via shuffles, ONE barrier/step.
__global__ void __launch_bounds__(THREADS, 1)
lstm_main(const float* __restrict__ x, const float* __restrict__ lin_b,
          float* __restrict__ out) {
    // h duplicated: h_shd[g][buf][row][b] = (h,h) for batch b  (32B per row)
    __shared__ __align__(16) ull h_shd[2][2][KROWS][4];
    __shared__ float redp[2][2][8][4];     // [grp][t&1][warp-in-group][batch]

    const int tid  = threadIdx.x;
    const int g    = tid >> 8;
    const int gtid = tid & 255;
    const int w    = gtid >> 5;        // warp within group (0..7) -> j block
    const int lane = tid & 31;
    const int q    = lane >> 3;        // k-quarter AND owned batch
    const int j8   = lane & 7;
    const int j    = w * 8 + j8;       // hidden unit
    const int q0   = q & 1;
    const int q1   = (q >> 1) & 1;
    const int b0   = blockIdx.x * 8 + g * 4;

    // Register-resident U rows q*13 .. q*13+12, gate-packed pairs (52 regs)
    ull u_if[KQ], u_go[KQ];
#pragma unroll
    for (int kk = 0; kk < KQ; kk++) {
        float4 u = g_U4[(q * KQ + kk) * JP + j];
        u_if[kk] = pk2(u.x, u.y);
        u_go[kk] = pk2(u.z, u.w);
    }
    const float4 wv  = g_W4[j];
    const float  lw  = g_L[j];
    const float  lbv = lin_b[0];

    // init h: zeros; bias row 51 = (1,1) in BOTH buffers (never rewritten)
    for (int i = tid; i < 2 * 2 * KROWS * 4; i += THREADS) {
        int row = (i >> 2) % KROWS;
        ((ull*)h_shd)[i] = (row == HIDDEN) ? pk2(1.f, 1.f) : 0ULL;
    }
    __syncthreads();

    float c  = 0.f;                          // cell state for (unit j, batch q)
    float xq = x[(b0 + q) * L_SEQ + 0];      // x for my batch, t=0

    for (int t = 0; t < L_SEQ; ++t) {
        const int rb = t & 1, wb = rb ^ 1, tb = t & 1;

        // Parity-relative base pointers: slots 0,1 = my q1-pair's batches,
        // slots 2,3 = other pair's. Fixed per thread -> zero selects in loop.
        const ulonglong2* hA =
            (const ulonglong2*)&h_shd[g][rb][q * KQ][q1 * 2];        // slots 0,1
        const ulonglong2* hB =
            (const ulonglong2*)&h_shd[g][rb][q * KQ][(q1 ^ 1) * 2];  // slots 2,3

        // ---- phase A: my 13 k-rows, 4 batch slots ----
        ull a0if = 0ULL, a0go = 0ULL, a1if = 0ULL, a1go = 0ULL;
        ull a2if = 0ULL, a2go = 0ULL, a3if = 0ULL, a3go = 0ULL;
#pragma unroll
        for (int kk = 0; kk < KQ; kk++) {
            ulonglong2 p = hA[kk * 2];     // (h,h) slot0, (h,h) slot1 — LDS.128
            ulonglong2 r = hB[kk * 2];     // (h,h) slot2, (h,h) slot3
            a0if = f2fma(p.x, u_if[kk], a0if); a0go = f2fma(p.x, u_go[kk], a0go);
            a1if = f2fma(p.y, u_if[kk], a1if); a1go = f2fma(p.y, u_go[kk], a1go);
            a2if = f2fma(r.x, u_if[kk], a2if); a2go = f2fma(r.x, u_go[kk], a2go);
            a3if = f2fma(r.y, u_if[kk], a3if); a3go = f2fma(r.y, u_go[kk], a3go);
        }

        // prefetch next x (hidden under butterfly/update)
        float xn = x[(b0 + q) * L_SEQ + ((t + 1 < L_SEQ) ? t + 1 : t)];

        // ---- butterfly stage 1 (xor16, q1 flip): partner's slots 2,3 are my batches 0,1
        a0if = f2add(a0if, shfl_xor64(a2if, 16));
        a0go = f2add(a0go, shfl_xor64(a2go, 16));
        a1if = f2add(a1if, shfl_xor64(a3if, 16));
        a1go = f2add(a1go, shfl_xor64(a3go, 16));
        // ---- stage 2 (xor8, q0 flip): redundant both-batch completion
        a0if = f2add(a0if, shfl_xor64(a0if, 8));
        a0go = f2add(a0go, shfl_xor64(a0go, 8));
        a1if = f2add(a1if, shfl_xor64(a1if, 8));
        a1go = f2add(a1go, shfl_xor64(a1go, 8));
        // my batch within the pair: q = q1*2 + q0 -> slot q0
        ull s_if = q0 ? a1if : a0if;
        ull s_go = q0 ? a1go : a0go;

        // ---- update c/h for (j, batch q) ----
        float gi, gf, gg, go;
        up2(gi, gf, s_if);
        up2(gg, go, s_go);
        gi = fmaf(xq, wv.x, gi);
        gf = fmaf(xq, wv.y, gf);
        gg = fmaf(xq, wv.z, gg);
        go = fmaf(xq, wv.w, go);
        c = fmaf(gf, c, gi * gg);               // faithful: no sigmoids
        float h = go * fast_tanh(c);
        if (j < HIDDEN) h_shd[g][wb][j][q] = pk2(h, h);

        // ---- output partial: reduce over j8 octet ----
        float prod = h * lw;
        prod += __shfl_xor_sync(0xffffffffu, prod, 1);
        prod += __shfl_xor_sync(0xffffffffu, prod, 2);
        prod += __shfl_xor_sync(0xffffffffu, prod, 4);
        if (j8 == 0) redp[g][tb][w][q] = prod;

        xq = xn;
        group_bar(g + 1);

        // ---- output for step t (4 threads per group; overlaps next phase A) ----
        if (gtid < 4) {
            int b = gtid;
            float v = lbv;
#pragma unroll
            for (int ww = 0; ww < 8; ww++) v += redp[g][tb][ww][b];
            out[(b0 + b) * L_SEQ + t] = v;
        }
    }
}

extern "C" void kernel_launch(void* const* d_in, const int* in_sizes, int n_in,
                              void* d_out, int out_size) {
    (void)in_sizes; (void)n_in; (void)out_size;
    const float* x     = (const float*)d_in[0];
    const float* W_w   = (const float*)d_in[1];
    const float* W_b   = (const float*)d_in[2];
    const float* U_w   = (const float*)d_in[3];
    const float* U_b   = (const float*)d_in[4];
    const float* lin_w = (const float*)d_in[5];
    const float* lin_b = (const float*)d_in[6];
    // d_in[7] = future (static 0) — ignored.

    prep_kernel<<<26, 128>>>(W_w, W_b, U_w, U_b, lin_w);
    lstm_main<<<NBLK, THREADS>>>(x, lin_b, (float*)d_out);
}

// round 9
// speedup vs baseline: 1.5022x; 1.5022x over previous
#include <cuda_runtime.h>

#define HIDDEN 51
#define JP 64
#define KT 18            // k-rows per third; 3*18 = 54: rows 0..50 U, 51 bias, 52..53 zero-pad
#define TROWS 54
#define NBG 4            // batches per group
#define L_SEQ 1000
#define NBLK 128
#define GROUP 192        // threads per group (3 thirds x 64 j)
#define THREADS 384      // 2 groups

typedef unsigned long long ull;

// Gate-interleaved weights: g_U4[row*JP + j] = (i,f,g,o); row 51 = combined bias
__device__ float4 g_U4[TROWS * JP];
__device__ float4 g_W4[JP];   // x weights per j
__device__ float  g_L[JP];    // lin_w per j

// ---------- f32x2 helpers ----------
__device__ __forceinline__ ull pk2(float lo, float hi) {
    ull r; asm("mov.b64 %0, {%1, %2};" : "=l"(r) : "f"(lo), "f"(hi)); return r;
}
__device__ __forceinline__ void up2(float& lo, float& hi, ull v) {
    asm("mov.b64 {%0, %1}, %2;" : "=f"(lo), "=f"(hi) : "l"(v));
}
__device__ __forceinline__ ull f2fma(ull a, ull b, ull c) {
    ull d; asm("fma.rn.f32x2 %0, %1, %2, %3;" : "=l"(d) : "l"(a), "l"(b), "l"(c)); return d;
}
__device__ __forceinline__ ull f2add(ull a, ull b) {
    ull d; asm("add.rn.f32x2 %0, %1, %2;" : "=l"(d) : "l"(a), "l"(b)); return d;
}
// accurate fast tanh: 1 - 2/(exp(2x)+1); saturates correctly at +-inf
__device__ __forceinline__ float fast_tanh(float xv) {
    float e;
    asm("ex2.approx.f32 %0, %1;" : "=f"(e) : "f"(xv * 2.8853900817779268f));
    float r;
    asm("rcp.approx.f32 %0, %1;" : "=f"(r) : "f"(e + 1.0f));
    return fmaf(-2.0f, r, 1.0f);
}
__device__ __forceinline__ void group_bar(int barid) {
    asm volatile("bar.sync %0, %1;" :: "r"(barid), "r"(GROUP) : "memory");
}

// ---------- prep ----------
__global__ void prep_kernel(const float* __restrict__ W_w, const float* __restrict__ W_b,
                            const float* __restrict__ U_w, const float* __restrict__ U_b,
                            const float* __restrict__ lin_w) {
    int i = blockIdx.x * 128 + threadIdx.x;   // 0 .. 3455 (54 rows x 64 j)
    if (i >= TROWS * JP) return;
    int k = i >> 6, j = i & 63;
    float4 u = make_float4(0.f, 0.f, 0.f, 0.f);
    if (j < HIDDEN) {
        if (k < HIDDEN) {
            u.x = U_w[(0 * HIDDEN + j) * HIDDEN + k];
            u.y = U_w[(1 * HIDDEN + j) * HIDDEN + k];
            u.z = U_w[(2 * HIDDEN + j) * HIDDEN + k];
            u.w = U_w[(3 * HIDDEN + j) * HIDDEN + k];
        } else if (k == HIDDEN) {             // row 51 = combined bias (h == 1)
            u.x = W_b[0 * HIDDEN + j] + U_b[0 * HIDDEN + j];
            u.y = W_b[1 * HIDDEN + j] + U_b[1 * HIDDEN + j];
            u.z = W_b[2 * HIDDEN + j] + U_b[2 * HIDDEN + j];
            u.w = W_b[3 * HIDDEN + j] + U_b[3 * HIDDEN + j];
        }                                      // rows 52,53 stay zero (pad)
    }
    g_U4[i] = u;
    if (i < JP) {
        float4 w = make_float4(0.f, 0.f, 0.f, 0.f);
        float lw = 0.f;
        if (i < HIDDEN) {
            w.x = W_w[0 * HIDDEN + i]; w.y = W_w[1 * HIDDEN + i];
            w.z = W_w[2 * HIDDEN + i]; w.w = W_w[3 * HIDDEN + i];
            lw = lin_w[i];
        }
        g_W4[i] = w; g_L[i] = lw;
    }
}

// ---------- main ----------
// 384 threads = 2 groups x 192. Group: 4 batches, k split in 3 thirds (18 rows each).
// Group thread = third*64 + j. U = 72 regs/thread -> no spill at reg cap 170.
// Phase B: third 0 updates batches 0,1; third 1 updates 2,3; third 2 idles at the bar.
__global__ void __launch_bounds__(THREADS, 1)
lstm_main(const float* __restrict__ x, const float* __restrict__ lin_b,
          float* __restrict__ out) {
    __shared__ __align__(16) float      h_sh[2][2][JP][NBG];   // compact [row][batch]
    __shared__ __align__(16) ulonglong2 psum[2][3][NBG][JP];   // [grp][third][batch][j]
    __shared__ float redp[2][4][2];                            // [grp][upd-warp][slot]

    const int tid   = threadIdx.x;
    const int g     = (tid >= GROUP) ? 1 : 0;
    const int gtid  = tid - g * GROUP;
    const int third = gtid >> 6;       // k-third (0..2)
    const int j     = gtid & 63;       // hidden unit
    const int lane  = tid & 31;
    const int wgrp  = gtid >> 5;       // warp within group (0..5); 0..3 are updaters
    const int b0    = blockIdx.x * 8 + g * 4;
    const bool upd  = (third < 2);     // updater thirds

    // Register-resident U rows third*18 .. third*18+17, gate-packed pairs (72 regs)
    ull u_if[KT], u_go[KT];
#pragma unroll
    for (int kk = 0; kk < KT; kk++) {
        float4 u = g_U4[(third * KT + kk) * JP + j];
        u_if[kk] = pk2(u.x, u.y);
        u_go[kk] = pk2(u.z, u.w);
    }
    const float4 wv  = g_W4[j];
    const float  lw  = g_L[j];
    const float  lbv = lin_b[0];

    // init h: zeros; bias row 51 = 1 in BOTH buffers
    for (int i = tid; i < 2 * 2 * JP * NBG; i += THREADS) {
        int row = (i >> 2) & 63;
        ((float*)h_sh)[i] = (row == HIDDEN) ? 1.0f : 0.0f;
    }
    __syncthreads();

    // cell state + x for my 2 phase-B batches (b = third*2 + s), updaters only
    float c[2] = {0.f, 0.f};
    float xq[2] = {0.f, 0.f};
    if (upd) {
#pragma unroll
        for (int s = 0; s < 2; s++) xq[s] = x[(b0 + third * 2 + s) * L_SEQ + 0];
    }

    for (int t = 0; t < L_SEQ; ++t) {
        const int rb = t & 1, wb = rb ^ 1;

        // ---- phase A: my 18 k-rows, all 4 batches (R2-style compact-h loop) ----
        ull a_if0 = 0ULL, a_go0 = 0ULL, a_if1 = 0ULL, a_go1 = 0ULL;
        ull a_if2 = 0ULL, a_go2 = 0ULL, a_if3 = 0ULL, a_go3 = 0ULL;
        const float4* hr = (const float4*)&h_sh[g][rb][third * KT][0];
#pragma unroll
        for (int kk = 0; kk < KT; kk++) {
            float4 hq = hr[kk];                 // LDS.128 broadcast: 4 batches
            ull h0 = pk2(hq.x, hq.x), h1 = pk2(hq.y, hq.y);
            ull h2 = pk2(hq.z, hq.z), h3 = pk2(hq.w, hq.w);
            a_if0 = f2fma(h0, u_if[kk], a_if0); a_go0 = f2fma(h0, u_go[kk], a_go0);
            a_if1 = f2fma(h1, u_if[kk], a_if1); a_go1 = f2fma(h1, u_go[kk], a_go1);
            a_if2 = f2fma(h2, u_if[kk], a_if2); a_go2 = f2fma(h2, u_go[kk], a_go2);
            a_if3 = f2fma(h3, u_if[kk], a_if3); a_go3 = f2fma(h3, u_go[kk], a_go3);
        }
        { ulonglong2 v; v.x = a_if0; v.y = a_go0; psum[g][third][0][j] = v; }
        { ulonglong2 v; v.x = a_if1; v.y = a_go1; psum[g][third][1][j] = v; }
        { ulonglong2 v; v.x = a_if2; v.y = a_go2; psum[g][third][2][j] = v; }
        { ulonglong2 v; v.x = a_if3; v.y = a_go3; psum[g][third][3][j] = v; }

        // prefetch next x (hidden under barrier + phase B)
        float xn[2] = {0.f, 0.f};
        if (upd) {
            int tn = (t + 1 < L_SEQ) ? t + 1 : t;
#pragma unroll
            for (int s = 0; s < 2; s++) xn[s] = x[(b0 + third * 2 + s) * L_SEQ + tn];
        }

        group_bar(g + 1);

        // ---- phase B: combine 3 thirds for (j, my 2 batches), update c/h ----
        if (upd) {
            float prod[2];
#pragma unroll
            for (int s = 0; s < 2; s++) {
                int b = third * 2 + s;
                ulonglong2 p0 = psum[g][0][b][j];
                ulonglong2 p1 = psum[g][1][b][j];
                ulonglong2 p2 = psum[g][2][b][j];
                ull s_if = f2add(f2add(p0.x, p1.x), p2.x);
                ull s_go = f2add(f2add(p0.y, p1.y), p2.y);
                float gi, gf, gg, go;
                up2(gi, gf, s_if);
                up2(gg, go, s_go);
                gi = fmaf(xq[s], wv.x, gi);
                gf = fmaf(xq[s], wv.y, gf);
                gg = fmaf(xq[s], wv.z, gg);
                go = fmaf(xq[s], wv.w, go);
                c[s] = fmaf(gf, c[s], gi * gg);     // faithful: no sigmoids
                float h = go * fast_tanh(c[s]);
                if (j == HIDDEN) h = 1.0f;          // keep bias row
                h_sh[g][wb][j][b] = h;
                prod[s] = h * lw;
                xq[s] = xn[s];
            }
            // reduce over j within warp (warp covers 32 consecutive j)
#pragma unroll
            for (int off = 16; off >= 1; off >>= 1) {
                prod[0] += __shfl_xor_sync(0xffffffffu, prod[0], off);
                prod[1] += __shfl_xor_sync(0xffffffffu, prod[1], off);
            }
            if (lane == 0) { redp[g][wgrp][0] = prod[0]; redp[g][wgrp][1] = prod[1]; }
        }

        group_bar(g + 1);

        // ---- output for step t (4 threads per group; overlaps next phase A) ----
        if (gtid < 4) {
            int b = gtid;
            int wbase = (b >> 1) << 1;   // b0,b1 from warps 0,1 (third0); b2,b3 from 2,3
            out[(b0 + b) * L_SEQ + t] = redp[g][wbase][b & 1] + redp[g][wbase + 1][b & 1] + lbv;
        }
    }
}

extern "C" void kernel_launch(void* const* d_in, const int* in_sizes, int n_in,
                              void* d_out, int out_size) {
    (void)in_sizes; (void)n_in; (void)out_size;
    const float* x     = (const float*)d_in[0];
    const float* W_w   = (const float*)d_in[1];
    const float* W_b   = (const float*)d_in[2];
    const float* U_w   = (const float*)d_in[3];
    const float* U_b   = (const float*)d_in[4];
    const float* lin_w = (const float*)d_in[5];
    const float* lin_b = (const float*)d_in[6];
    // d_in[7] = future (static 0) — ignored.

    prep_kernel<<<27, 128>>>(W_w, W_b, U_w, U_b, lin_w);
    lstm_main<<<NBLK, THREADS>>>(x, lin_b, (float*)d_out);
}

// round 10
// speedup vs baseline: 1.6064x; 1.0694x over previous
#include <cuda_runtime.h>

#define HIDDEN 51
#define JP 64
#define KH 26            // k-rows per half; 52 = 51 + 1 bias-fold row... (R2 layout: 26+26, bias via init fma)
#define L_SEQ 1000
#define NBLK 128
#define NBG 4            // batches per group
#define THREADS 256      // 2 groups x 128

typedef unsigned long long ull;

// Preprocessed weights (gate-interleaved): [k=0..51][j=0..63] -> (i,f,g,o)
__device__ float4 g_U4[2 * KH * JP];
__device__ float4 g_W4[JP];   // x weights per j, gates interleaved
__device__ float4 g_B4[JP];   // W_b + U_b per j, gates interleaved
__device__ float  g_L[JP];    // lin_w per j

// ---------- f32x2 helpers (exact packed fp32) ----------
__device__ __forceinline__ ull pk2(float lo, float hi) {
    ull r; asm("mov.b64 %0, {%1, %2};" : "=l"(r) : "f"(lo), "f"(hi)); return r;
}
__device__ __forceinline__ void up2(float& lo, float& hi, ull v) {
    asm("mov.b64 {%0, %1}, %2;" : "=f"(lo), "=f"(hi) : "l"(v));
}
__device__ __forceinline__ ull f2fma(ull a, ull b, ull c) {
    ull d; asm("fma.rn.f32x2 %0, %1, %2, %3;" : "=l"(d) : "l"(a), "l"(b), "l"(c)); return d;
}
__device__ __forceinline__ ull f2add(ull a, ull b) {
    ull d; asm("add.rn.f32x2 %0, %1, %2;" : "=l"(d) : "l"(a), "l"(b)); return d;
}
// fast accurate tanh: 1 - 2/(exp(2x)+1) via ex2.approx + rcp.approx (~1e-7 abs err)
__device__ __forceinline__ float fast_tanh(float xv) {
    float e;
    asm("ex2.approx.f32 %0, %1;" : "=f"(e) : "f"(xv * 2.8853900817779268f));
    float r;
    asm("rcp.approx.f32 %0, %1;" : "=f"(r) : "f"(e + 1.0f));
    return fmaf(-2.0f, r, 1.0f);
}
__device__ __forceinline__ void group_bar(int barid) {
    asm volatile("bar.sync %0, %1;" :: "r"(barid), "r"(128) : "memory");
}

// ---------- prep: reorder weights into gate-interleaved padded layout ----------
__global__ void prep_kernel(const float* __restrict__ W_w, const float* __restrict__ W_b,
                            const float* __restrict__ U_w, const float* __restrict__ U_b,
                            const float* __restrict__ lin_w) {
    int i = blockIdx.x * 128 + threadIdx.x;   // 0 .. 3327
    int k = i >> 6, j = i & 63;
    float4 u = make_float4(0.f, 0.f, 0.f, 0.f);
    if (k < HIDDEN && j < HIDDEN) {
        u.x = U_w[(0 * HIDDEN + j) * HIDDEN + k];
        u.y = U_w[(1 * HIDDEN + j) * HIDDEN + k];
        u.z = U_w[(2 * HIDDEN + j) * HIDDEN + k];
        u.w = U_w[(3 * HIDDEN + j) * HIDDEN + k];
    }
    g_U4[i] = u;
    if (i < JP) {
        float4 w = make_float4(0.f, 0.f, 0.f, 0.f);
        float4 b = make_float4(0.f, 0.f, 0.f, 0.f);
        float lw = 0.f;
        if (i < HIDDEN) {
            w.x = W_w[0 * HIDDEN + i]; w.y = W_w[1 * HIDDEN + i];
            w.z = W_w[2 * HIDDEN + i]; w.w = W_w[3 * HIDDEN + i];
            b.x = W_b[0 * HIDDEN + i] + U_b[0 * HIDDEN + i];
            b.y = W_b[1 * HIDDEN + i] + U_b[1 * HIDDEN + i];
            b.z = W_b[2 * HIDDEN + i] + U_b[2 * HIDDEN + i];
            b.w = W_b[3 * HIDDEN + i] + U_b[3 * HIDDEN + i];
            lw = lin_w[i];
        }
        g_W4[i] = w; g_B4[i] = b; g_L[i] = lw;
    }
}

// ---------- main recurrent kernel ----------
// R2 skeleton: 256 threads = 2 INDEPENDENT groups of 128 (own batches, own named
// barrier). Group: 4 batches; half = k-half; j = hidden unit.
// R10 deltas: (1) groups deliberately anti-phased via a startup delay on group 1;
// (2) output shuffle-reduction moved after bar2, out store lagged one step.
__global__ void __launch_bounds__(THREADS, 1)
lstm_main(const float* __restrict__ x, const float* __restrict__ lin_b,
          float* __restrict__ out) {
    __shared__ __align__(16) float  h_sh[2][JP][NBG];        // [group][unit][batch]
    __shared__ __align__(16) float4 psum[2][2][NBG][JP];     // [group][half][batch][j]
    __shared__ float redp[2][2][4][2];                       // [group][t&1][warp-in-grp][slot]

    const int tid   = threadIdx.x;
    const int g     = tid >> 7;        // group 0/1
    const int gtid  = tid & 127;
    const int half  = gtid >> 6;       // k-half
    const int j     = gtid & 63;       // hidden unit
    const int lane  = tid & 31;
    const int wg    = gtid >> 5;       // warp within group 0..3
    const int barid = g + 1;           // named barrier per group
    const int b0    = blockIdx.x * (2 * NBG) + g * NBG;

    // Register-resident U rows for (half, j): 26 x {(i,f),(g,o)} f32x2
    ull u_if[KH], u_go[KH];
#pragma unroll
    for (int kk = 0; kk < KH; kk++) {
        float4 u = g_U4[(half * KH + kk) * JP + j];
        u_if[kk] = pk2(u.x, u.y);
        u_go[kk] = pk2(u.z, u.w);
    }
    float4 wv = g_W4[j], bv = g_B4[j];
    const ull w_if = pk2(wv.x, wv.y), w_go = pk2(wv.z, wv.w);
    const ull b_if = pk2(bv.x, bv.y), b_go = pk2(bv.z, bv.w);
    const float lw  = g_L[j];
    const float lbv = lin_b[0];

    // This thread's cell state: 2 batches (half 0 -> b 0,1; half 1 -> b 2,3)
    float c[2] = {0.f, 0.f};

    // zero h
    for (int i = gtid; i < JP * NBG; i += 128) ((float*)h_sh[g])[i] = 0.f;

    // preload x for t=0
    float xn[NBG];
#pragma unroll
    for (int q = 0; q < NBG; q++) xn[q] = x[(b0 + q) * L_SEQ + 0];

    __syncthreads();

    // ---- anti-phase stagger: group 1 burns ~600 cycles of dependent FMAs ----
    if (g == 1) {
        float dly = (float)(tid + 1);
#pragma unroll 1
        for (int i = 0; i < 150; i++) dly = fmaf(dly, 0.99990f, 1e-7f);
        if (dly == 12345.678f) ((float*)h_sh)[0] = dly;   // never true; defeats DCE
    }

    for (int t = 0; t < L_SEQ; ++t) {
        // ---- phase A: partial gates for 4 batches (this thread's k-half) ----
        ull a_if[NBG], a_go[NBG];
#pragma unroll
        for (int q = 0; q < NBG; q++) {
            ull x2 = pk2(xn[q], xn[q]);
            a_if[q] = (half == 0) ? f2fma(x2, w_if, b_if) : pk2(0.f, 0.f);
            a_go[q] = (half == 0) ? f2fma(x2, w_go, b_go) : pk2(0.f, 0.f);
        }
#pragma unroll
        for (int kk = 0; kk < KH; kk++) {
            float4 hq = *(const float4*)&h_sh[g][half * KH + kk][0];
            ull h0 = pk2(hq.x, hq.x), h1 = pk2(hq.y, hq.y);
            ull h2 = pk2(hq.z, hq.z), h3 = pk2(hq.w, hq.w);
            a_if[0] = f2fma(h0, u_if[kk], a_if[0]); a_go[0] = f2fma(h0, u_go[kk], a_go[0]);
            a_if[1] = f2fma(h1, u_if[kk], a_if[1]); a_go[1] = f2fma(h1, u_go[kk], a_go[1]);
            a_if[2] = f2fma(h2, u_if[kk], a_if[2]); a_go[2] = f2fma(h2, u_go[kk], a_go[2]);
            a_if[3] = f2fma(h3, u_if[kk], a_if[3]); a_go[3] = f2fma(h3, u_go[kk], a_go[3]);
        }
#pragma unroll
        for (int q = 0; q < NBG; q++) {
            ulonglong2 v; v.x = a_if[q]; v.y = a_go[q];
            *(ulonglong2*)&psum[g][half][q][j] = v;
        }

        group_bar(barid);

        // ---- lagged output store for step t-1 (redp writes ordered by bar above) ----
        if (t > 0 && gtid < NBG) {
            int b = gtid, pb = (t - 1) & 1;
            int wbase = (b >> 1) << 1;
            out[(b0 + b) * L_SEQ + (t - 1)] =
                redp[g][pb][wbase][b & 1] + redp[g][pb][wbase + 1][b & 1] + lbv;
        }

        // ---- prefetch next x (latency hidden under phase B) ----
        {
            int tn = (t + 1 < L_SEQ) ? t + 1 : t;
#pragma unroll
            for (int q = 0; q < NBG; q++) xn[q] = x[(b0 + q) * L_SEQ + tn];
        }

        // ---- phase B: combine halves, update c/h for THIS thread's 2 batches ----
        float prod[2];
#pragma unroll
        for (int s = 0; s < 2; s++) {
            int b = half * 2 + s;
            ulonglong2 p0 = *(const ulonglong2*)&psum[g][0][b][j];
            ulonglong2 p1 = *(const ulonglong2*)&psum[g][1][b][j];
            ull s_if = f2add(p0.x, p1.x);
            ull s_go = f2add(p0.y, p1.y);
            float gi, gf, gg, go;
            up2(gi, gf, s_if);
            up2(gg, go, s_go);
            c[s] = fmaf(gf, c[s], gi * gg);     // f*c + i*g (faithful: no sigmoids!)
            float h = go * fast_tanh(c[s]);
            h_sh[g][j][b] = h;
            prod[s] = h * lw;
        }

        group_bar(barid);

        // ---- output reduction AFTER the barrier: overlaps next phase A ----
#pragma unroll
        for (int off = 16; off >= 1; off >>= 1) {
            prod[0] += __shfl_xor_sync(0xffffffffu, prod[0], off);
            prod[1] += __shfl_xor_sync(0xffffffffu, prod[1], off);
        }
        if (lane == 0) {
            redp[g][t & 1][wg][0] = prod[0];
            redp[g][t & 1][wg][1] = prod[1];
        }
    }

    // ---- tail: flush output for the final step ----
    group_bar(barid);
    if (gtid < NBG) {
        int b = gtid, pb = (L_SEQ - 1) & 1;
        int wbase = (b >> 1) << 1;
        out[(b0 + b) * L_SEQ + (L_SEQ - 1)] =
            redp[g][pb][wbase][b & 1] + redp[g][pb][wbase + 1][b & 1] + lbv;
    }
}

extern "C" void kernel_launch(void* const* d_in, const int* in_sizes, int n_in,
                              void* d_out, int out_size) {
    (void)in_sizes; (void)n_in; (void)out_size;
    const float* x     = (const float*)d_in[0];
    const float* W_w   = (const float*)d_in[1];
    const float* W_b   = (const float*)d_in[2];
    const float* U_w   = (const float*)d_in[3];
    const float* U_b   = (const float*)d_in[4];
    const float* lin_w = (const float*)d_in[5];
    const float* lin_b = (const float*)d_in[6];
    // d_in[7] = future (static 0) — ignored.

    prep_kernel<<<26, 128>>>(W_w, W_b, U_w, U_b, lin_w);
    lstm_main<<<NBLK, THREADS>>>(x, lin_b, (float*)d_out);
}